// round 1
// baseline (speedup 1.0000x reference)
#include <cuda_runtime.h>
#include <mma.h>

using namespace nvcuda;

// ---------------- problem constants ----------------
#define N0v 400000
#define N1v 200000
#define N2v 100000
#define N3v 50000
#define E0v 3200000
#define E1v 1600000
#define E2v 800000

// ---------------- scratch (device globals; no allocation allowed) ----------
__device__ __align__(16) float g_h1[(size_t)N2v * 256];   // layer0 out (only rows < N2 needed)
__device__ __align__(16) float g_h2[(size_t)N3v * 256];   // layer1 out (only rows < N3 needed)
__device__ __align__(16) float g_agg[(size_t)N2v * 128];  // 12.8M floats, reused by all layers
__device__ int   g_cnt[N1v];
__device__ int   g_rowptr[N1v];
__device__ int   g_cursor[N1v];
__device__ float g_dis[N1v];
__device__ int   g_csr[E0v];
__device__ int   g_bsums[256];

// ---------------- small utility kernels ----------------
__global__ void k_zero_cnt(int n) {
    int i = blockIdx.x * blockDim.x + threadIdx.x;
    if (i < n) g_cnt[i] = 0;
}

__global__ void k_count(const int* __restrict__ col, int E) {
    int e = blockIdx.x * blockDim.x + threadIdx.x;
    if (e < E) atomicAdd(&g_cnt[col[e]], 1);
}

__global__ void k_dis(int n_dst, float fill) {
    int i = blockIdx.x * blockDim.x + threadIdx.x;
    if (i < n_dst) g_dis[i] = rsqrtf((float)g_cnt[i] + fill);
}

// Hillis-Steele block scan -> exclusive per-block prefix + block sums
__global__ void k_scan1(int n) {
    __shared__ int s[1024];
    int tid = threadIdx.x;
    int i = blockIdx.x * 1024 + tid;
    int v = (i < n) ? g_cnt[i] : 0;
    s[tid] = v;
    __syncthreads();
    #pragma unroll
    for (int off = 1; off < 1024; off <<= 1) {
        int t = (tid >= off) ? s[tid - off] : 0;
        __syncthreads();
        s[tid] += t;
        __syncthreads();
    }
    if (i < n) g_rowptr[i] = s[tid] - v;
    if (tid == 1023) g_bsums[blockIdx.x] = s[1023];
}

__global__ void k_scan2(int nb) {  // exclusive scan of block sums (nb <= 256)
    __shared__ int s[256];
    int tid = threadIdx.x;
    int v = (tid < nb) ? g_bsums[tid] : 0;
    s[tid] = v;
    __syncthreads();
    #pragma unroll
    for (int off = 1; off < 256; off <<= 1) {
        int t = (tid >= off) ? s[tid - off] : 0;
        __syncthreads();
        s[tid] += t;
        __syncthreads();
    }
    if (tid < nb) g_bsums[tid] = s[tid] - v;
}

__global__ void k_scan3(int n) {
    int i = blockIdx.x * 1024 + threadIdx.x;
    if (i < n) {
        int v = g_rowptr[i] + g_bsums[blockIdx.x];
        g_rowptr[i] = v;
        g_cursor[i] = v;
    }
}

__global__ void k_fill(const int* __restrict__ row, const int* __restrict__ col, int E) {
    int e = blockIdx.x * blockDim.x + threadIdx.x;
    if (e < E) {
        int c = col[e];
        int p = atomicAdd(&g_cursor[c], 1);
        g_csr[p] = row[e];
    }
}

// ---------------- aggregation: one warp per destination ----------------
// SRC: 0 -> x param, 1 -> g_h1, 2 -> g_h2
template <int F, int SRC>
__global__ void k_aggregate(const float* __restrict__ xin, int n_out, int n_dst, float fill) {
    const float* __restrict__ x = (SRC == 0) ? xin : (SRC == 1) ? (const float*)g_h1 : (const float*)g_h2;
    int gw = (blockIdx.x * blockDim.x + threadIdx.x) >> 5;
    int lane = threadIdx.x & 31;
    if (gw >= n_out) return;
    int c = gw;
    float dc = g_dis[c];
    constexpr int V = F / 128;
    float4 acc[V];
    {
        const float4* xc = (const float4*)(x + (size_t)c * F);
        float sc = fill * dc * dc;
        #pragma unroll
        for (int v = 0; v < V; v++) {
            float4 t = xc[lane + 32 * v];
            acc[v] = make_float4(sc * t.x, sc * t.y, sc * t.z, sc * t.w);
        }
    }
    int beg = g_rowptr[c];
    int num = g_cnt[c];
    for (int j0 = 0; j0 < num; j0 += 32) {
        int r = (j0 + lane < num) ? g_csr[beg + j0 + lane] : 0;
        int m = min(32, num - j0);
        for (int t = 0; t < m; t++) {
            int rr = __shfl_sync(0xffffffffu, r, t);
            if (rr < n_dst) {  // dis[row]=0 for row >= n_dst: skip
                float coef = g_dis[rr] * dc;
                const float4* xr = (const float4*)(x + (size_t)rr * F);
                #pragma unroll
                for (int v = 0; v < V; v++) {
                    float4 u = xr[lane + 32 * v];
                    acc[v].x += coef * u.x;
                    acc[v].y += coef * u.y;
                    acc[v].z += coef * u.z;
                    acc[v].w += coef * u.w;
                }
            }
        }
    }
    float4* o = (float4*)(g_agg + (size_t)c * F);
    #pragma unroll
    for (int v = 0; v < V; v++) o[lane + 32 * v] = acc[v];
}

// ---------------- GEMM: g_agg[M,K] @ W[K,256] + b, optional relu ----------------
// tf32 WMMA, 64x64 block tile, 4 warps (2x2), 32x32 per warp.
// DST: 0 -> g_h1, 1 -> g_h2, 2 -> out param
template <int K, bool RELU, int DST>
__global__ __launch_bounds__(128) void k_gemm(const float* __restrict__ W,
                                              const float* __restrict__ bias,
                                              float* __restrict__ outp, int M) {
    float* __restrict__ out = (DST == 0) ? (float*)g_h1 : (DST == 1) ? (float*)g_h2 : outp;
    constexpr int BM = 64, BN = 64, BK = 32;
    __shared__ float sA[BM][BK + 4];
    __shared__ float sB[BK][BN + 4];
    __shared__ float sC[BM][BN + 4];

    int tid = threadIdx.x;
    int warp = tid >> 5;
    int wm = warp >> 1;  // 0..1
    int wn = warp & 1;   // 0..1
    int m0 = blockIdx.x * BM;
    int n0 = blockIdx.y * BN;
    const float* __restrict__ A = g_agg;

    wmma::fragment<wmma::accumulator, 16, 16, 8, float> acc[2][2];
    #pragma unroll
    for (int i = 0; i < 2; i++)
        #pragma unroll
        for (int j = 0; j < 2; j++) wmma::fill_fragment(acc[i][j], 0.0f);

    for (int k0 = 0; k0 < K; k0 += BK) {
        // A tile 64x32 (guard rows >= M with zeros)
        #pragma unroll
        for (int it = 0; it < 4; it++) {
            int idx = tid + it * 128;      // 0..511 float4 slots
            int r = idx >> 3;              // 8 float4 per row
            int ck = (idx & 7) << 2;
            float4 v = make_float4(0.f, 0.f, 0.f, 0.f);
            int gr = m0 + r;
            if (gr < M) v = *(const float4*)(A + (size_t)gr * K + (k0 + ck));
            sA[r][ck + 0] = wmma::__float_to_tf32(v.x);
            sA[r][ck + 1] = wmma::__float_to_tf32(v.y);
            sA[r][ck + 2] = wmma::__float_to_tf32(v.z);
            sA[r][ck + 3] = wmma::__float_to_tf32(v.w);
        }
        // B tile 32x64 from W[K,256]
        #pragma unroll
        for (int it = 0; it < 4; it++) {
            int idx = tid + it * 128;
            int r = idx >> 4;              // 16 float4 per row
            int cn = (idx & 15) << 2;
            float4 v = *(const float4*)(W + (size_t)(k0 + r) * 256 + (n0 + cn));
            sB[r][cn + 0] = wmma::__float_to_tf32(v.x);
            sB[r][cn + 1] = wmma::__float_to_tf32(v.y);
            sB[r][cn + 2] = wmma::__float_to_tf32(v.z);
            sB[r][cn + 3] = wmma::__float_to_tf32(v.w);
        }
        __syncthreads();

        #pragma unroll
        for (int kk = 0; kk < BK; kk += 8) {
            wmma::fragment<wmma::matrix_a, 16, 16, 8, wmma::precision::tf32, wmma::row_major> af[2];
            wmma::fragment<wmma::matrix_b, 16, 16, 8, wmma::precision::tf32, wmma::row_major> bf[2];
            #pragma unroll
            for (int i = 0; i < 2; i++)
                wmma::load_matrix_sync(af[i], &sA[wm * 32 + i * 16][kk], BK + 4);
            #pragma unroll
            for (int j = 0; j < 2; j++)
                wmma::load_matrix_sync(bf[j], &sB[kk][wn * 32 + j * 16], BN + 4);
            #pragma unroll
            for (int i = 0; i < 2; i++)
                #pragma unroll
                for (int j = 0; j < 2; j++)
                    wmma::mma_sync(acc[i][j], af[i], bf[j], acc[i][j]);
        }
        __syncthreads();
    }

    // epilogue: stage to smem, add bias (+relu), vectorized store
    #pragma unroll
    for (int i = 0; i < 2; i++)
        #pragma unroll
        for (int j = 0; j < 2; j++)
            wmma::store_matrix_sync(&sC[wm * 32 + i * 16][wn * 32 + j * 16], acc[i][j],
                                    BN + 4, wmma::mem_row_major);
    __syncthreads();

    #pragma unroll
    for (int it = 0; it < 8; it++) {
        int idx = tid + it * 128;  // 0..1023 float4 over 64x64
        int r = idx >> 4;
        int cn = (idx & 15) << 2;
        int gr = m0 + r;
        if (gr < M) {
            float4 v = *(const float4*)(&sC[r][cn]);
            float4 bb = *(const float4*)(bias + n0 + cn);
            v.x += bb.x; v.y += bb.y; v.z += bb.z; v.w += bb.w;
            if (RELU) {
                v.x = fmaxf(v.x, 0.f); v.y = fmaxf(v.y, 0.f);
                v.z = fmaxf(v.z, 0.f); v.w = fmaxf(v.w, 0.f);
            }
            *(float4*)(out + (size_t)gr * 256 + (n0 + cn)) = v;
        }
    }
}

// ---------------- per-layer driver ----------------
template <int F, int SRC, int DST, bool RELU>
static void run_layer(const float* xsrc, const int* eidx, int E, int n_dst, int n_out,
                      float fill, const float* W, const float* bias, float* out) {
    const int* row = eidx;
    const int* col = eidx + E;
    k_zero_cnt<<<(n_dst + 255) / 256, 256>>>(n_dst);
    k_count<<<(E + 255) / 256, 256>>>(col, E);
    k_dis<<<(n_dst + 255) / 256, 256>>>(n_dst, fill);
    int nb = (n_dst + 1023) / 1024;
    k_scan1<<<nb, 1024>>>(n_dst);
    k_scan2<<<1, 256>>>(nb);
    k_scan3<<<nb, 1024>>>(n_dst);
    k_fill<<<(E + 255) / 256, 256>>>(row, col, E);
    {
        long long warps = n_out;
        int blocks = (int)((warps * 32 + 255) / 256);
        k_aggregate<F, SRC><<<blocks, 256>>>(xsrc, n_out, n_dst, fill);
    }
    {
        dim3 grid((n_out + 63) / 64, 4);
        k_gemm<F, RELU, DST><<<grid, 128>>>(W, bias, out, n_out);
    }
}

extern "C" void kernel_launch(void* const* d_in, const int* in_sizes, int n_in,
                              void* d_out, int out_size) {
    const float* x  = (const float*)d_in[0];
    const int*   e0 = (const int*)d_in[1];
    const int*   e1 = (const int*)d_in[2];
    const int*   e2 = (const int*)d_in[3];
    const float* W0 = (const float*)d_in[4];
    const float* b0 = (const float*)d_in[5];
    const float* W1 = (const float*)d_in[6];
    const float* b1 = (const float*)d_in[7];
    const float* W2 = (const float*)d_in[8];
    const float* b2 = (const float*)d_in[9];
    float* out = (float*)d_out;

    // Layer 0: x[N0,128] -> h1 rows < N2 (only rows consumed by layer 1)
    run_layer<128, 0, 0, true>(x, e0, E0v, N1v, N2v, 2.0f, W0, b0, nullptr);
    // Layer 1: h1[N2,256] -> h2 rows < N3
    run_layer<256, 1, 1, true>(nullptr, e1, E1v, N2v, N3v, 2.0f, W1, b1, nullptr);
    // Layer 2: h2[N3,256] -> out[N3,256], fill=1, no relu
    run_layer<256, 2, 2, false>(nullptr, e2, E2v, N3v, N3v, 1.0f, W2, b2, out);
}

// round 2
// speedup vs baseline: 1.6320x; 1.6320x over previous
#include <cuda_runtime.h>
#include <cuda_fp16.h>
#include <mma.h>

using namespace nvcuda;

// ---------------- problem constants ----------------
#define N1v 200000
#define N2v 100000
#define N3v 50000
#define TNv 350000              // N1+N2+N3 concatenated target space
#define LB0 0
#define LB1 200000
#define LB2 300000
#define E0v 3200000
#define E1v 1600000
#define E2v 800000
#define TEv 5600000

// ---------------- scratch (device globals) ----------------
__device__ __align__(16) __half g_x16[(size_t)N1v * 128];   // fp16 copy of x rows < N1
__device__ __align__(16) __half g_h1[(size_t)N2v * 256];    // layer0 out (rows < N2)
__device__ __align__(16) __half g_h2[(size_t)N3v * 256];    // layer1 out (rows < N3)
__device__ __align__(16) __half g_agg[(size_t)N2v * 128];   // 12.8M halves (>= 50k*256)
__device__ int   g_cnt[TNv];     // filtered (useful-edge) counts
__device__ int   g_deg[TNv];     // full degree; reused as fill cursor
__device__ int   g_rowptr[TNv];
__device__ float g_dis[TNv];
__device__ int   g_csr[TEv];
__device__ int   g_bsums[512];

// ---------------- helpers ----------------
__device__ __forceinline__ float4 h4_to_f4(uint2 u) {
    __half2 a = *(__half2*)&u.x;
    __half2 b = *(__half2*)&u.y;
    float2 fa = __half22float2(a);
    float2 fb = __half22float2(b);
    return make_float4(fa.x, fa.y, fb.x, fb.y);
}
__device__ __forceinline__ uint2 f4_to_h4(float4 v) {
    __half2 a = __floats2half2_rn(v.x, v.y);
    __half2 b = __floats2half2_rn(v.z, v.w);
    uint2 r;
    r.x = *(unsigned*)&a;
    r.y = *(unsigned*)&b;
    return r;
}

// resolve a global edge id into (layer ptrs, local id, bases)
struct EdgeCtx { const int* p; int le; int E; int lb; int ndst; };
__device__ __forceinline__ EdgeCtx edge_ctx(int e, const int* e0, const int* e1, const int* e2) {
    EdgeCtx c;
    if (e < E0v)              { c.p = e0; c.le = e;             c.E = E0v; c.lb = LB0; c.ndst = N1v; }
    else if (e < E0v + E1v)   { c.p = e1; c.le = e - E0v;       c.E = E1v; c.lb = LB1; c.ndst = N2v; }
    else                      { c.p = e2; c.le = e - E0v - E1v; c.E = E2v; c.lb = LB2; c.ndst = N3v; }
    return c;
}

// ---------------- CSR build (all layers fused) ----------------
__global__ void k_zero() {
    int i = blockIdx.x * blockDim.x + threadIdx.x;
    if (i < TNv) { g_cnt[i] = 0; g_deg[i] = 0; }
}

__global__ void k_convert_x(const float* __restrict__ x) {
    int i = blockIdx.x * blockDim.x + threadIdx.x;   // float4 index
    const int n4 = N1v * 128 / 4;
    if (i < n4) {
        float4 v = ((const float4*)x)[i];
        ((uint2*)g_x16)[i] = f4_to_h4(v);
    }
}

__global__ void k_count_all(const int* __restrict__ e0, const int* __restrict__ e1,
                            const int* __restrict__ e2) {
    int e = blockIdx.x * blockDim.x + threadIdx.x;
    if (e >= TEv) return;
    EdgeCtx c = edge_ctx(e, e0, e1, e2);
    int row = c.p[c.le];
    int col = c.p[c.E + c.le];
    atomicAdd(&g_deg[c.lb + col], 1);
    if (row < c.ndst) atomicAdd(&g_cnt[c.lb + col], 1);
}

__global__ void k_dis_all() {
    int i = blockIdx.x * blockDim.x + threadIdx.x;
    if (i < TNv) {
        float fill = (i < LB2) ? 2.0f : 1.0f;
        g_dis[i] = rsqrtf((float)g_deg[i] + fill);
    }
}

__global__ void k_scan1() {
    __shared__ int s[1024];
    int tid = threadIdx.x;
    int i = blockIdx.x * 1024 + tid;
    int v = (i < TNv) ? g_cnt[i] : 0;
    s[tid] = v;
    __syncthreads();
    #pragma unroll
    for (int off = 1; off < 1024; off <<= 1) {
        int t = (tid >= off) ? s[tid - off] : 0;
        __syncthreads();
        s[tid] += t;
        __syncthreads();
    }
    if (i < TNv) g_rowptr[i] = s[tid] - v;
    if (tid == 1023) g_bsums[blockIdx.x] = s[1023];
}

__global__ void k_scan2(int nb) {  // nb <= 512
    __shared__ int s[512];
    int tid = threadIdx.x;
    int v = (tid < nb) ? g_bsums[tid] : 0;
    s[tid] = v;
    __syncthreads();
    #pragma unroll
    for (int off = 1; off < 512; off <<= 1) {
        int t = (tid >= off) ? s[tid - off] : 0;
        __syncthreads();
        s[tid] += t;
        __syncthreads();
    }
    if (tid < nb) g_bsums[tid] = s[tid] - v;
}

__global__ void k_scan3() {
    int i = blockIdx.x * 1024 + threadIdx.x;
    if (i < TNv) {
        int v = g_rowptr[i] + g_bsums[blockIdx.x];
        g_rowptr[i] = v;
        g_deg[i] = v;  // reuse as cursor
    }
}

__global__ void k_fill_all(const int* __restrict__ e0, const int* __restrict__ e1,
                           const int* __restrict__ e2) {
    int e = blockIdx.x * blockDim.x + threadIdx.x;
    if (e >= TEv) return;
    EdgeCtx c = edge_ctx(e, e0, e1, e2);
    int row = c.p[c.le];
    if (row < c.ndst) {
        int col = c.p[c.E + c.le];
        int pos = atomicAdd(&g_deg[c.lb + col], 1);
        g_csr[pos] = row;
    }
}

// ---------------- aggregation: one warp per destination ----------------
// SRC: 0 -> g_x16 (F=128), 1 -> g_h1 (F=256), 2 -> g_h2 (F=256)
template <int F, int SRC>
__global__ __launch_bounds__(256) void k_aggregate(int lb, int n_out, float fill) {
    const __half* __restrict__ x = (SRC == 0) ? g_x16 : (SRC == 1) ? g_h1 : g_h2;
    int gw = (blockIdx.x * blockDim.x + threadIdx.x) >> 5;
    int lane = threadIdx.x & 31;
    if (gw >= n_out) return;
    int c = gw;
    int base = lb + c;
    float dc = g_dis[base];
    constexpr int V = F / 128;
    float4 acc[V];
    {
        const __half* xc = x + (size_t)c * F;
        float sc = fill * dc * dc;
        #pragma unroll
        for (int v = 0; v < V; v++) {
            float4 t = h4_to_f4(*(const uint2*)(xc + 4 * lane + 128 * v));
            acc[v] = make_float4(sc * t.x, sc * t.y, sc * t.z, sc * t.w);
        }
    }
    int beg = g_rowptr[base];
    int num = g_cnt[base];
    for (int j0 = 0; j0 < num; j0 += 32) {
        int idx = j0 + lane;
        int r = (idx < num) ? g_csr[beg + idx] : 0;
        float dr = (idx < num) ? g_dis[lb + r] : 0.0f;
        int m = min(32, num - j0);
        for (int t = 0; t < m; t++) {
            int rr = __shfl_sync(0xffffffffu, r, t);
            float coef = __shfl_sync(0xffffffffu, dr, t) * dc;
            const __half* xr = x + (size_t)rr * F;
            #pragma unroll
            for (int v = 0; v < V; v++) {
                float4 u = h4_to_f4(*(const uint2*)(xr + 4 * lane + 128 * v));
                acc[v].x += coef * u.x;
                acc[v].y += coef * u.y;
                acc[v].z += coef * u.z;
                acc[v].w += coef * u.w;
            }
        }
    }
    uint2* o = (uint2*)(g_agg + (size_t)c * F);
    #pragma unroll
    for (int v = 0; v < V; v++) o[lane + 32 * v] = f4_to_h4(acc[v]);
}

// ---------------- GEMM: g_agg[M,K](fp16) @ W[K,256](fp32->fp16) + b ----------------
// fp16 WMMA m16n16k16 fp32-acc, 128x64 block tile, 8 warps (4x2), 32x32 per warp.
// DST: 0 -> g_h1 (half), 1 -> g_h2 (half), 2 -> out param (float)
template <int K, bool RELU, int DST>
__global__ __launch_bounds__(256) void k_gemm(const float* __restrict__ W,
                                              const float* __restrict__ bias,
                                              float* __restrict__ outp, int M) {
    constexpr int BM = 128, BN = 64, BK = 32;
    __shared__ __align__(32) __half sA[BM][BK + 8];   // ldm 40
    __shared__ __align__(32) __half sB[BK][BN + 8];   // ldm 72
    __shared__ __align__(32) float  sC[64][BN + 4];   // ldm 68 (two-phase epilogue)

    int tid = threadIdx.x;
    int warp = tid >> 5;
    int wm = warp >> 1;  // 0..3
    int wn = warp & 1;   // 0..1
    int m0 = blockIdx.x * BM;
    int n0 = blockIdx.y * BN;
    const __half* __restrict__ A = g_agg;

    wmma::fragment<wmma::accumulator, 16, 16, 16, float> acc[2][2];
    #pragma unroll
    for (int i = 0; i < 2; i++)
        #pragma unroll
        for (int j = 0; j < 2; j++) wmma::fill_fragment(acc[i][j], 0.0f);

    for (int k0 = 0; k0 < K; k0 += BK) {
        // A tile 128x32 halves: 1024 uint2 slots (4 halves each)
        #pragma unroll
        for (int it = 0; it < 4; it++) {
            int idx = tid + it * 256;
            int r = idx >> 3;            // 8 uint2 per row
            int ck = (idx & 7) << 2;
            uint2 v = make_uint2(0u, 0u);
            int gr = m0 + r;
            if (gr < M) v = *(const uint2*)(A + (size_t)gr * K + (k0 + ck));
            *(uint2*)(&sA[r][ck]) = v;
        }
        // B tile 32x64 from W[K,256] fp32 -> fp16
        #pragma unroll
        for (int it = 0; it < 2; it++) {
            int idx = tid + it * 256;
            int r = idx >> 4;            // 16 float4 per row
            int cn = (idx & 15) << 2;
            float4 v = *(const float4*)(W + (size_t)(k0 + r) * 256 + (n0 + cn));
            *(uint2*)(&sB[r][cn]) = f4_to_h4(v);
        }
        __syncthreads();

        #pragma unroll
        for (int kk = 0; kk < BK; kk += 16) {
            wmma::fragment<wmma::matrix_a, 16, 16, 16, __half, wmma::row_major> af[2];
            wmma::fragment<wmma::matrix_b, 16, 16, 16, __half, wmma::row_major> bf[2];
            #pragma unroll
            for (int i = 0; i < 2; i++)
                wmma::load_matrix_sync(af[i], &sA[wm * 32 + i * 16][kk], BK + 8);
            #pragma unroll
            for (int j = 0; j < 2; j++)
                wmma::load_matrix_sync(bf[j], &sB[kk][wn * 32 + j * 16], BN + 8);
            #pragma unroll
            for (int i = 0; i < 2; i++)
                #pragma unroll
                for (int j = 0; j < 2; j++)
                    wmma::mma_sync(acc[i][j], af[i], bf[j], acc[i][j]);
        }
        __syncthreads();
    }

    // two-phase epilogue: rows [0,64) then [64,128)
    #pragma unroll
    for (int ph = 0; ph < 2; ph++) {
        if ((wm >> 1) == ph) {
            #pragma unroll
            for (int i = 0; i < 2; i++)
                #pragma unroll
                for (int j = 0; j < 2; j++)
                    wmma::store_matrix_sync(&sC[(wm & 1) * 32 + i * 16][wn * 32 + j * 16],
                                            acc[i][j], BN + 4, wmma::mem_row_major);
        }
        __syncthreads();
        #pragma unroll
        for (int it = 0; it < 4; it++) {
            int idx = tid + it * 256;    // 1024 float4 over 64x64
            int r = idx >> 4;
            int cn = (idx & 15) << 2;
            int gr = m0 + ph * 64 + r;
            if (gr < M) {
                float4 v = *(const float4*)(&sC[r][cn]);
                float4 bb = *(const float4*)(bias + n0 + cn);
                v.x += bb.x; v.y += bb.y; v.z += bb.z; v.w += bb.w;
                if (RELU) {
                    v.x = fmaxf(v.x, 0.f); v.y = fmaxf(v.y, 0.f);
                    v.z = fmaxf(v.z, 0.f); v.w = fmaxf(v.w, 0.f);
                }
                if (DST == 2) {
                    *(float4*)(outp + (size_t)gr * 256 + (n0 + cn)) = v;
                } else {
                    __half* h = (DST == 0) ? g_h1 : g_h2;
                    *(uint2*)(h + (size_t)gr * 256 + (n0 + cn)) = f4_to_h4(v);
                }
            }
        }
        __syncthreads();
    }
}

extern "C" void kernel_launch(void* const* d_in, const int* in_sizes, int n_in,
                              void* d_out, int out_size) {
    const float* x  = (const float*)d_in[0];
    const int*   e0 = (const int*)d_in[1];
    const int*   e1 = (const int*)d_in[2];
    const int*   e2 = (const int*)d_in[3];
    const float* W0 = (const float*)d_in[4];
    const float* b0 = (const float*)d_in[5];
    const float* W1 = (const float*)d_in[6];
    const float* b1 = (const float*)d_in[7];
    const float* W2 = (const float*)d_in[8];
    const float* b2 = (const float*)d_in[9];
    float* out = (float*)d_out;

    // CSR build for all 3 layers, fused + dead-edge filtered
    k_zero<<<(TNv + 255) / 256, 256>>>();
    k_convert_x<<<(N1v * 128 / 4 + 255) / 256, 256>>>(x);
    k_count_all<<<(TEv + 255) / 256, 256>>>(e0, e1, e2);
    k_dis_all<<<(TNv + 255) / 256, 256>>>();
    int nb = (TNv + 1023) / 1024;   // 342
    k_scan1<<<nb, 1024>>>();
    k_scan2<<<1, 512>>>(nb);
    k_scan3<<<nb, 1024>>>();
    k_fill_all<<<(TEv + 255) / 256, 256>>>(e0, e1, e2);

    // Layer 0: x16[<N1,128] -> agg[N2,128] -> h1[N2,256] (relu)
    k_aggregate<128, 0><<<(N2v * 32 + 255) / 256, 256>>>(LB0, N2v, 2.0f);
    { dim3 g((N2v + 127) / 128, 4); k_gemm<128, true, 0><<<g, 256>>>(W0, b0, nullptr, N2v); }
    // Layer 1: h1[<N2,256] -> agg[N3,256] -> h2[N3,256] (relu)
    k_aggregate<256, 1><<<(N3v * 32 + 255) / 256, 256>>>(LB1, N3v, 2.0f);
    { dim3 g((N3v + 127) / 128, 4); k_gemm<256, true, 1><<<g, 256>>>(W1, b1, nullptr, N3v); }
    // Layer 2: h2[<N3,256] -> agg[N3,256] -> out[N3,256] (fill=1, no relu)
    k_aggregate<256, 2><<<(N3v * 32 + 255) / 256, 256>>>(LB2, N3v, 1.0f);
    { dim3 g((N3v + 127) / 128, 4); k_gemm<256, false, 2><<<g, 256>>>(W2, b2, out, N3v); }
}

// round 5
// speedup vs baseline: 1.6422x; 1.0063x over previous
#include <cuda_runtime.h>
#include <cuda_fp16.h>
#include <mma.h>
#include <cstdint>

using namespace nvcuda;

// ---------------- problem constants ----------------
#define N1v 200000
#define N2v 100000
#define N3v 50000
#define TNv 350000              // N1+N2+N3 concatenated target space
#define LB0 0
#define LB1 200000
#define LB2 300000
#define E0v 3200000
#define E1v 1600000
#define E2v 800000
#define TEv 5600000

// ---------------- scratch (device globals) ----------------
__device__ __align__(16) __half g_x16[(size_t)N1v * 128];   // fp16 copy of x rows < N1
__device__ __align__(16) __half g_h1[(size_t)N2v * 256];    // layer0 out (rows < N2)
__device__ __align__(16) __half g_h2[(size_t)N3v * 256];    // layer1 out (rows < N3)
__device__ __align__(16) __half g_agg[(size_t)N2v * 128];
__device__ __align__(16) __half g_wt0[256 * 128];           // W0^T fp16 [N=256, K=128]
__device__ __align__(16) __half g_wt1[256 * 256];           // W1^T
__device__ __align__(16) __half g_wt2[256 * 256];           // W2^T
__device__ int   g_cnt[TNv];
__device__ int   g_deg[TNv];
__device__ int   g_rowptr[TNv];
__device__ float g_dis[TNv];
__device__ int   g_csr[TEv];
__device__ int   g_bsums[512];

// ---------------- fp16 pack helpers ----------------
__device__ __forceinline__ float4 h4_to_f4(uint2 u) {
    __half2 a = *(__half2*)&u.x;
    __half2 b = *(__half2*)&u.y;
    float2 fa = __half22float2(a);
    float2 fb = __half22float2(b);
    return make_float4(fa.x, fa.y, fb.x, fb.y);
}
__device__ __forceinline__ uint2 f4_to_h4(float4 v) {
    __half2 a = __floats2half2_rn(v.x, v.y);
    __half2 b = __floats2half2_rn(v.z, v.w);
    uint2 r;
    r.x = *(unsigned*)&a;
    r.y = *(unsigned*)&b;
    return r;
}

// ---------------- cp.async helpers ----------------
__device__ __forceinline__ uint32_t s2u(const void* p) {
    uint32_t a;
    asm("{ .reg .u64 t; cvta.to.shared.u64 t, %1; cvt.u32.u64 %0, t; }" : "=r"(a) : "l"(p));
    return a;
}
__device__ __forceinline__ void cp_async16(uint32_t saddr, const void* gaddr) {
    asm volatile("cp.async.cg.shared.global [%0], [%1], 16;" :: "r"(saddr), "l"(gaddr));
}
#define CP_COMMIT() asm volatile("cp.async.commit_group;" ::: "memory")
#define CP_WAIT(n)  asm volatile("cp.async.wait_group %0;" :: "n"(n) : "memory")

// ---------------- edge resolution ----------------
struct EdgeCtx { const int* p; int le; int E; int lb; int ndst; };
__device__ __forceinline__ EdgeCtx edge_ctx(int e, const int* e0, const int* e1, const int* e2) {
    EdgeCtx c;
    if (e < E0v)              { c.p = e0; c.le = e;             c.E = E0v; c.lb = LB0; c.ndst = N1v; }
    else if (e < E0v + E1v)   { c.p = e1; c.le = e - E0v;       c.E = E1v; c.lb = LB1; c.ndst = N2v; }
    else                      { c.p = e2; c.le = e - E0v - E1v; c.E = E2v; c.lb = LB2; c.ndst = N3v; }
    return c;
}

// ---------------- CSR build + conversions ----------------
__global__ void k_zero() {
    int i = blockIdx.x * blockDim.x + threadIdx.x;
    if (i < TNv) { g_cnt[i] = 0; g_deg[i] = 0; }
}

#define XN4 (N1v * 128 / 4)
__global__ void k_convert(const float* __restrict__ x, const float* __restrict__ W0,
                          const float* __restrict__ W1, const float* __restrict__ W2) {
    int i = blockIdx.x * blockDim.x + threadIdx.x;
    if (i < XN4) {
        float4 v = ((const float4*)x)[i];
        ((uint2*)g_x16)[i] = f4_to_h4(v);
    } else {
        int j = i - XN4;
        if (j < 128 * 256) {
            int k = j >> 8, n = j & 255;
            g_wt0[n * 128 + k] = __float2half(W0[j]);
        } else if (j < 128 * 256 + 65536) {
            int j2 = j - 128 * 256;
            int k = j2 >> 8, n = j2 & 255;
            g_wt1[n * 256 + k] = __float2half(W1[j2]);
        } else if (j < 128 * 256 + 2 * 65536) {
            int j3 = j - 128 * 256 - 65536;
            int k = j3 >> 8, n = j3 & 255;
            g_wt2[n * 256 + k] = __float2half(W2[j3]);
        }
    }
}

__global__ void k_count_all(const int* __restrict__ e0, const int* __restrict__ e1,
                            const int* __restrict__ e2) {
    int e = blockIdx.x * blockDim.x + threadIdx.x;
    if (e >= TEv) return;
    EdgeCtx c = edge_ctx(e, e0, e1, e2);
    int row = c.p[c.le];
    int col = c.p[c.E + c.le];
    atomicAdd(&g_deg[c.lb + col], 1);
    if (row < c.ndst) atomicAdd(&g_cnt[c.lb + col], 1);
}

__global__ void k_scan1() {
    __shared__ int s[1024];
    int tid = threadIdx.x;
    int i = blockIdx.x * 1024 + tid;
    int v = (i < TNv) ? g_cnt[i] : 0;
    s[tid] = v;
    __syncthreads();
    #pragma unroll
    for (int off = 1; off < 1024; off <<= 1) {
        int t = (tid >= off) ? s[tid - off] : 0;
        __syncthreads();
        s[tid] += t;
        __syncthreads();
    }
    if (i < TNv) g_rowptr[i] = s[tid] - v;
    if (tid == 1023) g_bsums[blockIdx.x] = s[1023];
}

__global__ void k_scan2(int nb) {
    __shared__ int s[512];
    int tid = threadIdx.x;
    int v = (tid < nb) ? g_bsums[tid] : 0;
    s[tid] = v;
    __syncthreads();
    #pragma unroll
    for (int off = 1; off < 512; off <<= 1) {
        int t = (tid >= off) ? s[tid - off] : 0;
        __syncthreads();
        s[tid] += t;
        __syncthreads();
    }
    if (tid < nb) g_bsums[tid] = s[tid] - v;
}

__global__ void k_scan3() {  // also computes dis
    int i = blockIdx.x * 1024 + threadIdx.x;
    if (i < TNv) {
        float fill = (i < LB2) ? 2.0f : 1.0f;
        g_dis[i] = rsqrtf((float)g_deg[i] + fill);
        int v = g_rowptr[i] + g_bsums[blockIdx.x];
        g_rowptr[i] = v;
        g_deg[i] = v;  // reuse as fill cursor
    }
}

__global__ void k_fill_all(const int* __restrict__ e0, const int* __restrict__ e1,
                           const int* __restrict__ e2) {
    int e = blockIdx.x * blockDim.x + threadIdx.x;
    if (e >= TEv) return;
    EdgeCtx c = edge_ctx(e, e0, e1, e2);
    int row = c.p[c.le];
    if (row < c.ndst) {
        int col = c.p[c.E + c.le];
        int pos = atomicAdd(&g_deg[c.lb + col], 1);
        g_csr[pos] = row;
    }
}

// ---------------- aggregation: one warp per destination ----------------
template <int F, int SRC>
__global__ __launch_bounds__(256) void k_aggregate(int lb, int n_out, float fill) {
    const __half* __restrict__ x = (SRC == 0) ? g_x16 : (SRC == 1) ? g_h1 : g_h2;
    int gw = (blockIdx.x * blockDim.x + threadIdx.x) >> 5;
    int lane = threadIdx.x & 31;
    if (gw >= n_out) return;
    int c = gw;
    int base = lb + c;
    float dc = g_dis[base];
    constexpr int V = F / 128;
    float4 acc[V], acc2[V];
    {
        const __half* xc = x + (size_t)c * F;
        float sc = fill * dc * dc;
        #pragma unroll
        for (int v = 0; v < V; v++) {
            float4 t = h4_to_f4(*(const uint2*)(xc + 4 * lane + 128 * v));
            acc[v] = make_float4(sc * t.x, sc * t.y, sc * t.z, sc * t.w);
            acc2[v] = make_float4(0.f, 0.f, 0.f, 0.f);
        }
    }
    int beg = g_rowptr[base];
    int num = g_cnt[base];
    for (int j0 = 0; j0 < num; j0 += 32) {
        int idx = j0 + lane;
        int r = (idx < num) ? g_csr[beg + idx] : 0;
        float dr = (idx < num) ? g_dis[lb + r] : 0.0f;
        int m = min(32, num - j0);
        int t = 0;
        for (; t + 2 <= m; t += 2) {  // unroll-by-2, dual accumulators for MLP
            int ra = __shfl_sync(0xffffffffu, r, t);
            int rb = __shfl_sync(0xffffffffu, r, t + 1);
            float ca = __shfl_sync(0xffffffffu, dr, t) * dc;
            float cb = __shfl_sync(0xffffffffu, dr, t + 1) * dc;
            const __half* xa = x + (size_t)ra * F;
            const __half* xb = x + (size_t)rb * F;
            #pragma unroll
            for (int v = 0; v < V; v++) {
                float4 ua = h4_to_f4(*(const uint2*)(xa + 4 * lane + 128 * v));
                float4 ub = h4_to_f4(*(const uint2*)(xb + 4 * lane + 128 * v));
                acc[v].x += ca * ua.x;  acc[v].y += ca * ua.y;
                acc[v].z += ca * ua.z;  acc[v].w += ca * ua.w;
                acc2[v].x += cb * ub.x; acc2[v].y += cb * ub.y;
                acc2[v].z += cb * ub.z; acc2[v].w += cb * ub.w;
            }
        }
        if (t < m) {
            int ra = __shfl_sync(0xffffffffu, r, t);
            float ca = __shfl_sync(0xffffffffu, dr, t) * dc;
            const __half* xa = x + (size_t)ra * F;
            #pragma unroll
            for (int v = 0; v < V; v++) {
                float4 ua = h4_to_f4(*(const uint2*)(xa + 4 * lane + 128 * v));
                acc[v].x += ca * ua.x; acc[v].y += ca * ua.y;
                acc[v].z += ca * ua.z; acc[v].w += ca * ua.w;
            }
        }
    }
    uint2* o = (uint2*)(g_agg + (size_t)c * F);
    #pragma unroll
    for (int v = 0; v < V; v++) {
        float4 s = make_float4(acc[v].x + acc2[v].x, acc[v].y + acc2[v].y,
                               acc[v].z + acc2[v].z, acc[v].w + acc2[v].w);
        o[lane + 32 * v] = f4_to_h4(s);
    }
}

// ---------------- GEMM: g_agg[M,K]h @ Wt[N,K]h -> out[M,256] ----------------
// fp16 wmma m16n16k16, fp32 acc. 128x128x32 block tile, 8 warps (2m x 4n),
// warp tile 64x32. cp.async 2-stage double buffering.
// WSEL picks the weight table (device global) INSIDE the kernel.
// DST: 0 -> g_h1 (half), 1 -> g_h2 (half), 2 -> outp (float)
template <int K, bool RELU, int DST, int WSEL>
__global__ __launch_bounds__(256) void k_gemm(const float* __restrict__ bias,
                                              float* __restrict__ outp, int M) {
    const __half* __restrict__ Wt =
        (WSEL == 0) ? (const __half*)g_wt0 :
        (WSEL == 1) ? (const __half*)g_wt1 : (const __half*)g_wt2;
    constexpr int BM = 128, BN = 128, BK = 32;
    constexpr int LDT = BK + 8;                     // 40 halves pitch (80B, 16B-aligned rows)
    constexpr int STAGE = BM * LDT;                 // halves per operand per stage
    // layout: [stage0 A | stage0 B | stage1 A | stage1 B]
    __shared__ __align__(16) __half smem[4 * STAGE];
    __half* sA[2] = { smem,             smem + 2 * STAGE };
    __half* sB[2] = { smem + STAGE,     smem + 3 * STAGE };

    int tid = threadIdx.x;
    int warp = tid >> 5;
    int wm = warp >> 2;        // 0..1  (64-row slab)
    int wn = warp & 3;         // 0..3  (32-col slab)
    int m0 = blockIdx.x * BM;
    int n0 = blockIdx.y * BN;
    const __half* __restrict__ A = g_agg;

    // cp.async indexing: 512 chunks of 16B per operand tile, 2 per thread
    int r0 = tid >> 1;               // rows 0..127, one row per 2 threads
    int c0 = (tid & 1) * 2;          // chunk 0/1 or 2/3

    auto load_stage = [&](int k0, int s) {
        #pragma unroll
        for (int q = 0; q < 2; q++) {
            int cc = c0 + q;                 // chunk in row: 0..3
            int kcol = k0 + cc * 8;
            int gr = m0 + r0; if (gr >= M) gr = 0;   // clamp; rows >= M never stored
            cp_async16(s2u(sA[s] + r0 * LDT + cc * 8), A + (size_t)gr * K + kcol);
            cp_async16(s2u(sB[s] + r0 * LDT + cc * 8), Wt + (size_t)(n0 + r0) * K + kcol);
        }
        CP_COMMIT();
    };

    wmma::fragment<wmma::accumulator, 16, 16, 16, float> acc[4][2];
    #pragma unroll
    for (int i = 0; i < 4; i++)
        #pragma unroll
        for (int j = 0; j < 2; j++) wmma::fill_fragment(acc[i][j], 0.0f);

    constexpr int KT = K / BK;
    load_stage(0, 0);

    #pragma unroll
    for (int kt = 0; kt < KT; kt++) {
        if (kt + 1 < KT) {
            load_stage((kt + 1) * BK, (kt + 1) & 1);
            CP_WAIT(1);
        } else {
            CP_WAIT(0);
        }
        __syncthreads();
        int s = kt & 1;
        #pragma unroll
        for (int kk = 0; kk < BK; kk += 16) {
            wmma::fragment<wmma::matrix_a, 16, 16, 16, __half, wmma::row_major> af[4];
            wmma::fragment<wmma::matrix_b, 16, 16, 16, __half, wmma::col_major> bf[2];
            #pragma unroll
            for (int i = 0; i < 4; i++)
                wmma::load_matrix_sync(af[i], sA[s] + (wm * 64 + i * 16) * LDT + kk, LDT);
            #pragma unroll
            for (int j = 0; j < 2; j++)
                wmma::load_matrix_sync(bf[j], sB[s] + (wn * 32 + j * 16) * LDT + kk, LDT);
            #pragma unroll
            for (int i = 0; i < 4; i++)
                #pragma unroll
                for (int j = 0; j < 2; j++)
                    wmma::mma_sync(acc[i][j], af[i], bf[j], acc[i][j]);
        }
        __syncthreads();   // protect stage buffer reused by next load
    }

    // epilogue: two phases of 64 rows through smem-as-float (reuse stage mem)
    float* sC = (float*)smem;          // 64 x 132 floats = 33.8KB <= 40KB
    constexpr int LDC = BN + 4;
    #pragma unroll
    for (int ph = 0; ph < 2; ph++) {
        if (wm == ph) {
            #pragma unroll
            for (int i = 0; i < 4; i++)
                #pragma unroll
                for (int j = 0; j < 2; j++)
                    wmma::store_matrix_sync(&sC[(i * 16) * LDC + wn * 32 + j * 16],
                                            acc[i][j], LDC, wmma::mem_row_major);
        }
        __syncthreads();
        #pragma unroll
        for (int it = 0; it < 8; it++) {
            int idx = tid + it * 256;        // 2048 float4 over 64x128
            int r = idx >> 5;
            int cn = (idx & 31) << 2;
            int gr = m0 + ph * 64 + r;
            if (gr < M) {
                float4 v = *(const float4*)(&sC[r * LDC + cn]);
                float4 bb = *(const float4*)(bias + n0 + cn);
                v.x += bb.x; v.y += bb.y; v.z += bb.z; v.w += bb.w;
                if (RELU) {
                    v.x = fmaxf(v.x, 0.f); v.y = fmaxf(v.y, 0.f);
                    v.z = fmaxf(v.z, 0.f); v.w = fmaxf(v.w, 0.f);
                }
                if (DST == 2) {
                    *(float4*)(outp + (size_t)gr * 256 + (n0 + cn)) = v;
                } else {
                    __half* h = (DST == 0) ? g_h1 : g_h2;
                    *(uint2*)(h + (size_t)gr * 256 + (n0 + cn)) = f4_to_h4(v);
                }
            }
        }
        __syncthreads();
    }
}

// ---------------- launch ----------------
extern "C" void kernel_launch(void* const* d_in, const int* in_sizes, int n_in,
                              void* d_out, int out_size) {
    const float* x  = (const float*)d_in[0];
    const int*   e0 = (const int*)d_in[1];
    const int*   e1 = (const int*)d_in[2];
    const int*   e2 = (const int*)d_in[3];
    const float* W0 = (const float*)d_in[4];
    const float* b0 = (const float*)d_in[5];
    const float* W1 = (const float*)d_in[6];
    const float* b1 = (const float*)d_in[7];
    const float* W2 = (const float*)d_in[8];
    const float* b2 = (const float*)d_in[9];
    float* out = (float*)d_out;

    k_zero<<<(TNv + 255) / 256, 256>>>();
    {
        int total = XN4 + 128 * 256 + 2 * 65536;
        k_convert<<<(total + 255) / 256, 256>>>(x, W0, W1, W2);
    }
    k_count_all<<<(TEv + 255) / 256, 256>>>(e0, e1, e2);
    int nb = (TNv + 1023) / 1024;
    k_scan1<<<nb, 1024>>>();
    k_scan2<<<1, 512>>>(nb);
    k_scan3<<<nb, 1024>>>();
    k_fill_all<<<(TEv + 255) / 256, 256>>>(e0, e1, e2);

    // Layer 0: agg over x16 -> GEMM K=128 -> h1 (relu)
    k_aggregate<128, 0><<<(N2v * 32 + 255) / 256, 256>>>(LB0, N2v, 2.0f);
    { dim3 g((N2v + 127) / 128, 2); k_gemm<128, true, 0, 0><<<g, 256>>>(b0, nullptr, N2v); }
    // Layer 1: agg over h1 -> GEMM K=256 -> h2 (relu)
    k_aggregate<256, 1><<<(N3v * 32 + 255) / 256, 256>>>(LB1, N3v, 2.0f);
    { dim3 g((N3v + 127) / 128, 2); k_gemm<256, true, 1, 1><<<g, 256>>>(b1, nullptr, N3v); }
    // Layer 2: agg over h2 -> GEMM K=256 -> out (fill=1, no relu)
    k_aggregate<256, 2><<<(N3v * 32 + 255) / 256, 256>>>(LB2, N3v, 1.0f);
    { dim3 g((N3v + 127) / 128, 2); k_gemm<256, false, 2, 2><<<g, 256>>>(b2, out, N3v); }
}